// round 2
// baseline (speedup 1.0000x reference)
#include <cuda_runtime.h>
#include <math.h>

#define NN 100000
#define NE 1600000
#define NF 133
#define HD 128

// ---- scratch (device globals: no allocation allowed in kernel_launch) ----
__device__ float d_g[NN * HD];     // g = dis[n] * (h @ W)[n]
__device__ float d_h[NN * HD];     // hidden activations between layers
__device__ int   d_cnt[NN];        // in-degree counts
__device__ int   d_rowptr[NN + 1]; // CSR row pointers (by dst)
__device__ int   d_head[NN];       // fill cursors
__device__ int   d_col[NE];        // CSR column (src) indices
__device__ float d_dis[NN];        // deg^{-1/2} with self loop

// ---------------- preprocessing ----------------

__global__ void zero_cnt_k() {
    int i = blockIdx.x * blockDim.x + threadIdx.x;
    if (i < NN) d_cnt[i] = 0;
}

__global__ void count_k(const int* __restrict__ ei) {
    int e = blockIdx.x * blockDim.x + threadIdx.x;
    if (e < NE) {
        int dst = ei[NE + e];
        atomicAdd(&d_cnt[dst], 1);
    }
}

// single-block scan: rowptr (exclusive), head copy, dis = rsqrt(deg+1)
__global__ void scan_k() {
    __shared__ int sums[1024];
    int t = threadIdx.x;
    const int CH = (NN + 1023) / 1024;  // 98
    int lo = t * CH;
    int hi = lo + CH; if (hi > NN) hi = NN;
    int s = 0;
    for (int i = lo; i < hi; i++) s += d_cnt[i];
    sums[t] = s;
    __syncthreads();
    // Hillis-Steele inclusive scan
    for (int off = 1; off < 1024; off <<= 1) {
        int v = 0;
        if (t >= off) v = sums[t - off];
        __syncthreads();
        sums[t] += v;
        __syncthreads();
    }
    int run = sums[t] - s;  // exclusive prefix for this chunk
    for (int i = lo; i < hi; i++) {
        int c = d_cnt[i];
        d_rowptr[i] = run;
        d_head[i]   = run;
        d_dis[i]    = rsqrtf((float)c + 1.0f);
        run += c;
    }
    if (t == 1023) d_rowptr[NN] = run;  // == NE
}

__global__ void fill_k(const int* __restrict__ ei) {
    int e = blockIdx.x * blockDim.x + threadIdx.x;
    if (e < NE) {
        int src = ei[e];
        int dst = ei[NE + e];
        int p = atomicAdd(&d_head[dst], 1);
        d_col[p] = src;
    }
}

// ---------------- per-layer GEMM:  g = dis[m] * (H @ W) ----------------
// Tile: 64 rows x 128 cols per block, 256 threads, 8x4 outputs/thread.
// hs stored transposed [k][row] so the inner loop is 2x LDS.128 (broadcast)
// for h plus 1x LDS.128 for w, feeding 32 FFMA.

__global__ void gemm_k(const float* __restrict__ Hext,
                       const float* __restrict__ W, int K) {
    __shared__ float hs[32 * 64];    // [kk][row]
    __shared__ float ws[32 * 128];   // [kk][col]
    const float* H = Hext ? Hext : d_h;

    int tid = threadIdx.x;
    int tx = tid & 31;   // col group: cols tx*4 .. tx*4+3
    int ty = tid >> 5;   // row group: rows ty*8 .. ty*8+7
    int m0 = blockIdx.x * 64;

    float acc[8][4];
    #pragma unroll
    for (int r = 0; r < 8; r++)
        #pragma unroll
        for (int c = 0; c < 4; c++) acc[r][c] = 0.0f;

    int nkc = (K + 31) / 32;
    for (int kc = 0; kc < nkc; kc++) {
        int k0 = kc * 32;
        // load h tile transposed: hs[kk*64 + r] = H[(m0+r)*K + k0+kk]
        for (int i = tid; i < 32 * 64; i += 256) {
            int kk = i >> 6, r = i & 63;
            int gm = m0 + r, gk = k0 + kk;
            hs[i] = (gm < NN && gk < K) ? H[gm * K + gk] : 0.0f;
        }
        // load w tile: ws[kk*128 + c] = W[(k0+kk)*128 + c]
        for (int i = tid; i < 32 * 128; i += 256) {
            int kk = i >> 7, c = i & 127;
            int gk = k0 + kk;
            ws[i] = (gk < K) ? W[gk * HD + c] : 0.0f;
        }
        __syncthreads();

        #pragma unroll
        for (int k = 0; k < 32; k++) {
            float4 w4 = *(const float4*)&ws[k * 128 + tx * 4];
            float4 ha = *(const float4*)&hs[k * 64 + ty * 8];
            float4 hb = *(const float4*)&hs[k * 64 + ty * 8 + 4];
            float hv[8] = {ha.x, ha.y, ha.z, ha.w, hb.x, hb.y, hb.z, hb.w};
            #pragma unroll
            for (int r = 0; r < 8; r++) {
                acc[r][0] += hv[r] * w4.x;
                acc[r][1] += hv[r] * w4.y;
                acc[r][2] += hv[r] * w4.z;
                acc[r][3] += hv[r] * w4.w;
            }
        }
        __syncthreads();
    }

    #pragma unroll
    for (int r = 0; r < 8; r++) {
        int gm = m0 + ty * 8 + r;
        if (gm < NN) {
            float sc = d_dis[gm];
            float4 o;
            o.x = acc[r][0] * sc; o.y = acc[r][1] * sc;
            o.z = acc[r][2] * sc; o.w = acc[r][3] * sc;
            *(float4*)&d_g[gm * HD + tx * 4] = o;
        }
    }
}

// ---------------- per-layer aggregation + bias + tanh ----------------
// one warp per node; lane owns a float4 slice of the 128-dim row.
// h_out[n] = tanh( dis[n] * (g[n] + sum_{e->n} g[src_e]) + b )

__global__ void agg_k(const float* __restrict__ bias,
                      float* __restrict__ outp) {
    int gw = (blockIdx.x * blockDim.x + threadIdx.x) >> 5;
    int lane = threadIdx.x & 31;
    if (gw >= NN) return;
    float* out = outp ? outp : d_h;

    int n = gw;
    float4 acc = *(const float4*)&d_g[n * HD + lane * 4];  // self term
    int lo = d_rowptr[n];
    int hi = d_rowptr[n + 1];
    #pragma unroll 4
    for (int e = lo; e < hi; e++) {
        int s = __ldg(&d_col[e]);
        float4 v = *(const float4*)&d_g[s * HD + lane * 4];
        acc.x += v.x; acc.y += v.y; acc.z += v.z; acc.w += v.w;
    }
    float sc = d_dis[n];
    float4 b = *(const float4*)&bias[lane * 4];
    float4 o;
    o.x = tanhf(sc * acc.x + b.x);
    o.y = tanhf(sc * acc.y + b.y);
    o.z = tanhf(sc * acc.z + b.z);
    o.w = tanhf(sc * acc.w + b.w);
    *(float4*)&out[n * HD + lane * 4] = o;
}

// ---------------- launch ----------------

extern "C" void kernel_launch(void* const* d_in, const int* in_sizes, int n_in,
                              void* d_out, int out_size) {
    const float* x  = (const float*)d_in[0];   // [NN, 133]
    const int*   ei = (const int*)d_in[1];     // [2, NE] int32 (JAX x64 disabled)
    const float* W[4] = {(const float*)d_in[2], (const float*)d_in[4],
                         (const float*)d_in[6], (const float*)d_in[8]};
    const float* B[4] = {(const float*)d_in[3], (const float*)d_in[5],
                         (const float*)d_in[7], (const float*)d_in[9]};
    float* out = (float*)d_out;

    // preprocessing (amortized over 4 layers)
    zero_cnt_k<<<(NN + 255) / 256, 256>>>();
    count_k<<<(NE + 255) / 256, 256>>>(ei);
    scan_k<<<1, 1024>>>();
    fill_k<<<(NE + 255) / 256, 256>>>(ei);

    const int GEMM_BLOCKS = (NN + 63) / 64;
    const int AGG_BLOCKS  = (NN * 32 + 255) / 256;

    // layer 0: input x (K=133)
    gemm_k<<<GEMM_BLOCKS, 256>>>(x, W[0], NF);
    agg_k<<<AGG_BLOCKS, 256>>>(B[0], nullptr);
    // layers 1..2: internal h (K=128)
    gemm_k<<<GEMM_BLOCKS, 256>>>(nullptr, W[1], HD);
    agg_k<<<AGG_BLOCKS, 256>>>(B[1], nullptr);
    gemm_k<<<GEMM_BLOCKS, 256>>>(nullptr, W[2], HD);
    agg_k<<<AGG_BLOCKS, 256>>>(B[2], nullptr);
    // layer 3: write to d_out
    gemm_k<<<GEMM_BLOCKS, 256>>>(nullptr, W[3], HD);
    agg_k<<<AGG_BLOCKS, 256>>>(B[3], out);
}

// round 3
// speedup vs baseline: 1.0911x; 1.0911x over previous
#include <cuda_runtime.h>
#include <math.h>
#include <stdint.h>

#define NN 100000
#define NE 1600000
#define NF 133
#define HD 128
#define PADH 132   // hs row stride (k-major, transposed): mult of 4 for LDS.128, mod-32=4 limits STS conflicts to 4-way

// ---- scratch (device globals: no allocation allowed in kernel_launch) ----
__device__ float d_g[NN * HD];     // g = dis[n] * (h @ W)[n]
__device__ float d_h[NN * HD];     // hidden activations between layers
__device__ int   d_cnt[NN];        // in-degree counts
__device__ int   d_rowptr[NN + 1]; // CSR row pointers (by dst)
__device__ int   d_head[NN];       // fill cursors
__device__ int   d_col[NE];        // CSR column (src) indices
__device__ float d_dis[NN];        // deg^{-1/2} with self loop

// ---------------- preprocessing ----------------

__global__ void zero_cnt_k() {
    int i = blockIdx.x * blockDim.x + threadIdx.x;
    if (i < NN) d_cnt[i] = 0;
}

__global__ void count_k(const int* __restrict__ ei) {
    int e = blockIdx.x * blockDim.x + threadIdx.x;
    if (e < NE) atomicAdd(&d_cnt[ei[NE + e]], 1);
}

// single-block scan: rowptr (exclusive), head copy, dis = rsqrt(deg+1)
__global__ void scan_k() {
    __shared__ int sums[1024];
    int t = threadIdx.x;
    const int CH = (NN + 1023) / 1024;  // 98
    int lo = t * CH;
    int hi = lo + CH; if (hi > NN) hi = NN;
    int s = 0;
    for (int i = lo; i < hi; i++) s += d_cnt[i];
    sums[t] = s;
    __syncthreads();
    for (int off = 1; off < 1024; off <<= 1) {
        int v = 0;
        if (t >= off) v = sums[t - off];
        __syncthreads();
        sums[t] += v;
        __syncthreads();
    }
    int run = sums[t] - s;
    for (int i = lo; i < hi; i++) {
        int c = d_cnt[i];
        d_rowptr[i] = run;
        d_head[i]   = run;
        d_dis[i]    = rsqrtf((float)c + 1.0f);
        run += c;
    }
    if (t == 1023) d_rowptr[NN] = run;  // == NE
}

__global__ void fill_k(const int* __restrict__ ei) {
    int e = blockIdx.x * blockDim.x + threadIdx.x;
    if (e < NE) {
        int src = ei[e];
        int dst = ei[NE + e];
        int p = atomicAdd(&d_head[dst], 1);
        d_col[p] = src;
    }
}

// ---------------- per-layer GEMM:  g = dis[m] * (H @ W) ----------------
// 128x128 tile, 256 threads, 8x8 outputs/thread held as 8x4 f32x2 packed
// along N. fma.rn.f32x2 (FFMA2) doubles fp32 FMA throughput per issue.

__global__ __launch_bounds__(256, 2)
void gemm_k(const float* __restrict__ Hext,
            const float* __restrict__ W, int K) {
    __shared__ float hs[32 * PADH];   // [kk][row], transposed, padded
    __shared__ float ws[32 * 128];    // [kk][col]
    const float* H = Hext ? Hext : d_h;

    int tid = threadIdx.x;
    int tx = tid & 15;    // col group: cols tx*8 .. tx*8+7
    int ty = tid >> 4;    // row group: rows ty*8 .. ty*8+7
    int m0 = blockIdx.x * 128;

    uint64_t acc[8][4];
    #pragma unroll
    for (int r = 0; r < 8; r++)
        #pragma unroll
        for (int c = 0; c < 4; c++) acc[r][c] = 0ULL;

    int nkc = (K + 31) / 32;
    for (int kc = 0; kc < nkc; kc++) {
        int k0 = kc * 32;
        // H tile: coalesced global read (consecutive tid -> consecutive k),
        // transposed store into padded smem.
        #pragma unroll
        for (int i = tid; i < 128 * 32; i += 256) {
            int r = i >> 5, kk = i & 31;
            int gm = m0 + r, gk = k0 + kk;
            hs[kk * PADH + r] = (gm < NN && gk < K) ? H[gm * K + gk] : 0.0f;
        }
        // W tile: float4 coalesced (W rows are 128 contiguous floats).
        #pragma unroll
        for (int j = tid; j < 32 * 32; j += 256) {
            int kk = j >> 5, c4 = j & 31;
            int gk = k0 + kk;
            float4 v = make_float4(0.f, 0.f, 0.f, 0.f);
            if (gk < K) v = *(const float4*)&W[gk * HD + c4 * 4];
            *(float4*)&ws[kk * 128 + c4 * 4] = v;
        }
        __syncthreads();

        #pragma unroll
        for (int k = 0; k < 32; k++) {
            // w: 8 floats = 4 natural f32x2 pairs
            ulonglong2 wab = *(const ulonglong2*)&ws[k * 128 + tx * 8];
            ulonglong2 wcd = *(const ulonglong2*)&ws[k * 128 + tx * 8 + 4];
            uint64_t wv[4] = {wab.x, wab.y, wcd.x, wcd.y};
            // h: 8 broadcast values, duplicated into both f32x2 halves
            float4 ha = *(const float4*)&hs[k * PADH + ty * 8];
            float4 hb = *(const float4*)&hs[k * PADH + ty * 8 + 4];
            float hv[8] = {ha.x, ha.y, ha.z, ha.w, hb.x, hb.y, hb.z, hb.w};
            uint64_t hp[8];
            #pragma unroll
            for (int r = 0; r < 8; r++)
                asm("mov.b64 %0, {%1, %1};" : "=l"(hp[r]) : "f"(hv[r]));
            #pragma unroll
            for (int r = 0; r < 8; r++)
                #pragma unroll
                for (int c = 0; c < 4; c++)
                    asm("fma.rn.f32x2 %0, %1, %2, %0;"
                        : "+l"(acc[r][c]) : "l"(hp[r]), "l"(wv[c]));
        }
        __syncthreads();
    }

    #pragma unroll
    for (int r = 0; r < 8; r++) {
        int gm = m0 + ty * 8 + r;
        if (gm < NN) {
            float sc = d_dis[gm];
            float o[8];
            #pragma unroll
            for (int c = 0; c < 4; c++) {
                float lo, hi;
                asm("mov.b64 {%0, %1}, %2;" : "=f"(lo), "=f"(hi) : "l"(acc[r][c]));
                o[2 * c]     = lo * sc;
                o[2 * c + 1] = hi * sc;
            }
            float4 o0 = make_float4(o[0], o[1], o[2], o[3]);
            float4 o1 = make_float4(o[4], o[5], o[6], o[7]);
            *(float4*)&d_g[gm * HD + tx * 8]     = o0;
            *(float4*)&d_g[gm * HD + tx * 8 + 4] = o1;
        }
    }
}

// ---------------- per-layer aggregation + bias + tanh ----------------
// one warp per node; lane owns a float4 slice of the 128-dim row.
// h_out[n] = tanh( dis[n] * (g[n] + sum_{e->n} g[src_e]) + b )

__global__ void agg_k(const float* __restrict__ bias,
                      float* __restrict__ outp) {
    int gw = (blockIdx.x * blockDim.x + threadIdx.x) >> 5;
    int lane = threadIdx.x & 31;
    if (gw >= NN) return;
    float* out = outp ? outp : d_h;

    int n = gw;
    float4 acc = *(const float4*)&d_g[n * HD + lane * 4];  // self term
    int lo = d_rowptr[n];
    int hi = d_rowptr[n + 1];
    #pragma unroll 4
    for (int e = lo; e < hi; e++) {
        int s = __ldg(&d_col[e]);
        float4 v = *(const float4*)&d_g[s * HD + lane * 4];
        acc.x += v.x; acc.y += v.y; acc.z += v.z; acc.w += v.w;
    }
    float sc = d_dis[n];
    float4 b = *(const float4*)&bias[lane * 4];
    float4 o;
    o.x = tanhf(sc * acc.x + b.x);
    o.y = tanhf(sc * acc.y + b.y);
    o.z = tanhf(sc * acc.z + b.z);
    o.w = tanhf(sc * acc.w + b.w);
    *(float4*)&out[n * HD + lane * 4] = o;
}

// ---------------- launch ----------------

extern "C" void kernel_launch(void* const* d_in, const int* in_sizes, int n_in,
                              void* d_out, int out_size) {
    const float* x  = (const float*)d_in[0];   // [NN, 133]
    const int*   ei = (const int*)d_in[1];     // [2, NE] int32
    const float* W[4] = {(const float*)d_in[2], (const float*)d_in[4],
                         (const float*)d_in[6], (const float*)d_in[8]};
    const float* B[4] = {(const float*)d_in[3], (const float*)d_in[5],
                         (const float*)d_in[7], (const float*)d_in[9]};
    float* out = (float*)d_out;

    zero_cnt_k<<<(NN + 255) / 256, 256>>>();
    count_k<<<(NE + 255) / 256, 256>>>(ei);
    scan_k<<<1, 1024>>>();
    fill_k<<<(NE + 255) / 256, 256>>>(ei);

    const int GEMM_BLOCKS = (NN + 127) / 128;
    const int AGG_BLOCKS  = (NN * 32 + 255) / 256;

    gemm_k<<<GEMM_BLOCKS, 256>>>(x, W[0], NF);
    agg_k<<<AGG_BLOCKS, 256>>>(B[0], nullptr);
    gemm_k<<<GEMM_BLOCKS, 256>>>(nullptr, W[1], HD);
    agg_k<<<AGG_BLOCKS, 256>>>(B[1], nullptr);
    gemm_k<<<GEMM_BLOCKS, 256>>>(nullptr, W[2], HD);
    agg_k<<<AGG_BLOCKS, 256>>>(B[2], nullptr);
    gemm_k<<<GEMM_BLOCKS, 256>>>(nullptr, W[3], HD);
    agg_k<<<AGG_BLOCKS, 256>>>(B[3], out);
}

// round 8
// speedup vs baseline: 1.1392x; 1.0441x over previous
#include <cuda_runtime.h>
#include <cuda_fp16.h>
#include <math.h>
#include <stdint.h>

#define NN 100000
#define NE 1600000
#define NF 133
#define HD 128
#define PADH 132

// ---- scratch (device globals) ----
__device__ __half d_gh[NN * HD];   // g = dis[n]*(h@W)[n], fp16 for gather bandwidth
__device__ float d_h[NN * HD];     // hidden activations between layers (fp32)
__device__ int   d_cnt[NN];
__device__ int   d_rowptr[NN + 1];
__device__ int   d_head[NN];
__device__ int   d_col[NE];
__device__ float d_dis[NN];

// ---------------- preprocessing ----------------

__global__ void zero_cnt_k() {
    int i = blockIdx.x * blockDim.x + threadIdx.x;
    if (i < NN) d_cnt[i] = 0;
}

__global__ void count_k(const int* __restrict__ ei) {
    int e = blockIdx.x * blockDim.x + threadIdx.x;
    if (e < NE) atomicAdd(&d_cnt[ei[NE + e]], 1);
}

__global__ void scan_k() {
    __shared__ int sums[1024];
    int t = threadIdx.x;
    const int CH = (NN + 1023) / 1024;
    int lo = t * CH;
    int hi = lo + CH; if (hi > NN) hi = NN;
    int s = 0;
    for (int i = lo; i < hi; i++) s += d_cnt[i];
    sums[t] = s;
    __syncthreads();
    for (int off = 1; off < 1024; off <<= 1) {
        int v = 0;
        if (t >= off) v = sums[t - off];
        __syncthreads();
        sums[t] += v;
        __syncthreads();
    }
    int run = sums[t] - s;
    for (int i = lo; i < hi; i++) {
        int c = d_cnt[i];
        d_rowptr[i] = run;
        d_head[i]   = run;
        d_dis[i]    = rsqrtf((float)c + 1.0f);
        run += c;
    }
    if (t == 1023) d_rowptr[NN] = run;
}

__global__ void fill_k(const int* __restrict__ ei) {
    int e = blockIdx.x * blockDim.x + threadIdx.x;
    if (e < NE) {
        int src = ei[e];
        int dst = ei[NE + e];
        int p = atomicAdd(&d_head[dst], 1);
        d_col[p] = src;
    }
}

// ---------------- per-layer GEMM:  g = dis[m] * (H @ W),  fp16 out ----------------
// 128x128 tile, 256 threads, 8x8 outputs/thread as 8x4 f32x2, FFMA2 inner loop.

__global__ __launch_bounds__(256, 2)
void gemm_k(const float* __restrict__ Hext,
            const float* __restrict__ W, int K) {
    __shared__ float hs[32 * PADH];   // [kk][row], transposed, padded
    __shared__ float ws[32 * 128];    // [kk][col]
    const float* H = Hext ? Hext : d_h;

    int tid = threadIdx.x;
    int tx = tid & 15;    // cols tx*8 .. tx*8+7
    int ty = tid >> 4;    // rows ty*8 .. ty*8+7
    int m0 = blockIdx.x * 128;

    uint64_t acc[8][4];
    #pragma unroll
    for (int r = 0; r < 8; r++)
        #pragma unroll
        for (int c = 0; c < 4; c++) acc[r][c] = 0ULL;

    int nkc = (K + 31) / 32;
    for (int kc = 0; kc < nkc; kc++) {
        int k0 = kc * 32;
        #pragma unroll
        for (int i = tid; i < 128 * 32; i += 256) {
            int r = i >> 5, kk = i & 31;
            int gm = m0 + r, gk = k0 + kk;
            hs[kk * PADH + r] = (gm < NN && gk < K) ? H[gm * K + gk] : 0.0f;
        }
        #pragma unroll
        for (int j = tid; j < 32 * 32; j += 256) {
            int kk = j >> 5, c4 = j & 31;
            int gk = k0 + kk;
            float4 v = make_float4(0.f, 0.f, 0.f, 0.f);
            if (gk < K) v = *(const float4*)&W[gk * HD + c4 * 4];
            *(float4*)&ws[kk * 128 + c4 * 4] = v;
        }
        __syncthreads();

        #pragma unroll
        for (int k = 0; k < 32; k++) {
            ulonglong2 wab = *(const ulonglong2*)&ws[k * 128 + tx * 8];
            ulonglong2 wcd = *(const ulonglong2*)&ws[k * 128 + tx * 8 + 4];
            uint64_t wv[4] = {wab.x, wab.y, wcd.x, wcd.y};
            float4 ha = *(const float4*)&hs[k * PADH + ty * 8];
            float4 hb = *(const float4*)&hs[k * PADH + ty * 8 + 4];
            float hv[8] = {ha.x, ha.y, ha.z, ha.w, hb.x, hb.y, hb.z, hb.w};
            uint64_t hp[8];
            #pragma unroll
            for (int r = 0; r < 8; r++)
                asm("mov.b64 %0, {%1, %1};" : "=l"(hp[r]) : "f"(hv[r]));
            #pragma unroll
            for (int r = 0; r < 8; r++)
                #pragma unroll
                for (int c = 0; c < 4; c++)
                    asm("fma.rn.f32x2 %0, %1, %2, %0;"
                        : "+l"(acc[r][c]) : "l"(hp[r]), "l"(wv[c]));
        }
        __syncthreads();
    }

    #pragma unroll
    for (int r = 0; r < 8; r++) {
        int gm = m0 + ty * 8 + r;
        if (gm < NN) {
            float sc = d_dis[gm];
            __half2 ph[4];
            #pragma unroll
            for (int c = 0; c < 4; c++) {
                float lo, hi;
                asm("mov.b64 {%0, %1}, %2;" : "=f"(lo), "=f"(hi) : "l"(acc[r][c]));
                ph[c] = __floats2half2_rn(lo * sc, hi * sc);
            }
            // 8 halves = 16B per thread; row = 16 tx-slots * 16B = 256B total
            *(uint4*)&d_gh[(size_t)gm * HD + tx * 8] = *(uint4*)ph;
        }
    }
}

// ---------------- per-layer aggregation + bias + tanh ----------------
// one warp per node; lane owns 4 halves (8B) of the 256B fp16 row
// (32 lanes x 4 halves = 128 = HD).
// h_out[n] = tanh( dis[n] * (g[n] + sum_{e->n} g[src_e]) + b )

__global__ void agg_k(const float* __restrict__ bias,
                      float* __restrict__ outp) {
    int gw = (blockIdx.x * blockDim.x + threadIdx.x) >> 5;
    int lane = threadIdx.x & 31;
    if (gw >= NN) return;
    float* out = outp ? outp : d_h;

    int n = gw;
    float2 acc[2];
    {   // self term
        uint2 raw = *(const uint2*)&d_gh[(size_t)n * HD + lane * 4];
        const __half2* hp = (const __half2*)&raw;
        acc[0] = __half22float2(hp[0]);
        acc[1] = __half22float2(hp[1]);
    }
    int lo = d_rowptr[n];
    int hi = d_rowptr[n + 1];
    for (int base = lo; base < hi; base += 32) {
        int idx = base + lane;
        int myc = (idx < hi) ? __ldg(&d_col[idx]) : 0;
        int cnt = hi - base; if (cnt > 32) cnt = 32;
        for (int j = 0; j < cnt; j++) {
            int s = __shfl_sync(0xffffffffu, myc, j);
            uint2 raw = __ldg((const uint2*)&d_gh[(size_t)s * HD + lane * 4]);
            const __half2* hp = (const __half2*)&raw;
            float2 v0 = __half22float2(hp[0]);
            float2 v1 = __half22float2(hp[1]);
            acc[0].x += v0.x; acc[0].y += v0.y;
            acc[1].x += v1.x; acc[1].y += v1.y;
        }
    }
    float sc = d_dis[n];
    float4 b = *(const float4*)&bias[lane * 4];
    float4 o;
    o.x = tanhf(sc * acc[0].x + b.x);
    o.y = tanhf(sc * acc[0].y + b.y);
    o.z = tanhf(sc * acc[1].x + b.z);
    o.w = tanhf(sc * acc[1].y + b.w);
    *(float4*)&out[(size_t)n * HD + lane * 4] = o;
}

// ---------------- launch ----------------

extern "C" void kernel_launch(void* const* d_in, const int* in_sizes, int n_in,
                              void* d_out, int out_size) {
    const float* x  = (const float*)d_in[0];   // [NN, 133]
    const int*   ei = (const int*)d_in[1];     // [2, NE] int32
    const float* W[4] = {(const float*)d_in[2], (const float*)d_in[4],
                         (const float*)d_in[6], (const float*)d_in[8]};
    const float* B[4] = {(const float*)d_in[3], (const float*)d_in[5],
                         (const float*)d_in[7], (const float*)d_in[9]};
    float* out = (float*)d_out;

    zero_cnt_k<<<(NN + 255) / 256, 256>>>();
    count_k<<<(NE + 255) / 256, 256>>>(ei);
    scan_k<<<1, 1024>>>();
    fill_k<<<(NE + 255) / 256, 256>>>(ei);

    const int GEMM_BLOCKS = (NN + 127) / 128;
    const int AGG_BLOCKS  = (NN * 32 + 255) / 256;

    gemm_k<<<GEMM_BLOCKS, 256>>>(x, W[0], NF);
    agg_k<<<AGG_BLOCKS, 256>>>(B[0], nullptr);
    gemm_k<<<GEMM_BLOCKS, 256>>>(nullptr, W[1], HD);
    agg_k<<<AGG_BLOCKS, 256>>>(B[1], nullptr);
    gemm_k<<<GEMM_BLOCKS, 256>>>(nullptr, W[2], HD);
    agg_k<<<AGG_BLOCKS, 256>>>(B[2], nullptr);
    gemm_k<<<GEMM_BLOCKS, 256>>>(nullptr, W[3], HD);
    agg_k<<<AGG_BLOCKS, 256>>>(B[3], out);
}